// round 9
// baseline (speedup 1.0000x reference)
#include <cuda_runtime.h>
#include <math.h>

// Problem constants
#define BB   64
#define TT   256
#define DD   1024
#define HH   1024
#define G4   4096      // 4*H
#define MROWS (BB*TT)  // 16384
#define NBLK 128u      // persistent grid size (<= SM count, all co-resident)

// Scratch (static device allocations — allowed; no cudaMalloc anywhere)
__device__ float g_xz[2][MROWS][G4];       // input projections, fwd/bwd (536 MB)
__device__ float g_h[2][2][BB][HH];        // h state, [buffer][dir][b][j]
__device__ unsigned g_bar;                 // grid barrier counter

// ---------------------------------------------------------------------------
// Packed f32x2 helpers: one FFMA2 = 2 fp32 MACs per fma-pipe issue.
// ---------------------------------------------------------------------------
typedef unsigned long long u64;

__device__ __forceinline__ u64 fma2_(u64 a, u64 b, u64 c) {
    u64 d;
    asm("fma.rn.f32x2 %0, %1, %2, %3;" : "=l"(d) : "l"(a), "l"(b), "l"(c));
    return d;
}
__device__ __forceinline__ u64 add2_(u64 a, u64 b) {
    u64 d;
    asm("add.rn.f32x2 %0, %1, %2;" : "=l"(d) : "l"(a), "l"(b));
    return d;
}
__device__ __forceinline__ u64 pack2_(float v) {   // (v, v)
    u64 d;
    asm("mov.b64 %0, {%1, %1};" : "=l"(d) : "r"(__float_as_uint(v)));
    return d;
}
__device__ __forceinline__ void unpack2_(u64 v, float& lo, float& hi) {
    asm("mov.b64 {%0, %1}, %2;" : "=f"(lo), "=f"(hi) : "l"(v));
}
__device__ __forceinline__ double ull_as_d(u64 v) {
    return __longlong_as_double((long long)v);
}

// ---------------------------------------------------------------------------
// Reset the grid-barrier counter (fresh on every graph replay).
// ---------------------------------------------------------------------------
__global__ void reset_kernel() { g_bar = 0u; }

// ---------------------------------------------------------------------------
// Input projection: g_xz[dir][b*T+t][g] = sum_d x[b,t,d] * W[d,g] + bias[g]
// FFMA2, double-buffered, single barrier. R9: next-chunk loads issued BEFORE
// __syncthreads so LDG latency overlaps the barrier + store phase.
// grid = (64, 128): blockIdx.x = dir*32 + ntile, blockIdx.y = mtile
// ---------------------------------------------------------------------------
__global__ __launch_bounds__(256)
void input_gemm_kernel(const float* __restrict__ x,
                       const float* __restrict__ Wf, const float* __restrict__ bf,
                       const float* __restrict__ Wb, const float* __restrict__ bb)
{
    const int dir = blockIdx.x >> 5;
    const int nt  = blockIdx.x & 31;
    const int m0  = blockIdx.y * 128;
    const int n0  = nt * 128;
    const float* __restrict__ W    = dir ? Wb : Wf;
    const float* __restrict__ bias = dir ? bb : bf;

    __shared__ float As[2][8][128];
    __shared__ float Bs[2][8][128];

    const int tid = threadIdx.x;
    const int tm = tid >> 4;
    const int tn = tid & 15;

    const int arow  = tid >> 1;
    const int acol4 = (tid & 1) * 4;
    const int brow  = tid >> 5;
    const int bcol  = (tid & 31) * 4;

    u64 acc2[8][4];
    #pragma unroll
    for (int i = 0; i < 8; i++)
        #pragma unroll
        for (int p = 0; p < 4; p++) acc2[i][p] = 0ull;

    const float* __restrict__ aptr = x + (size_t)(m0 + arow) * DD + acol4;
    const float* __restrict__ bptr = W + (size_t)brow * G4 + n0 + bcol;

    float4 av = *(const float4*)(aptr);
    float4 bv = *(const float4*)(bptr);

    const int NCHUNK = DD / 8;  // 128
    for (int c = 0; c < NCHUNK; c++) {
        const int buf = c & 1;
        As[buf][acol4 + 0][arow] = av.x;
        As[buf][acol4 + 1][arow] = av.y;
        As[buf][acol4 + 2][arow] = av.z;
        As[buf][acol4 + 3][arow] = av.w;
        *(float4*)&Bs[buf][brow][bcol] = bv;

        // issue next-chunk loads BEFORE the barrier (latency overlaps sync+compute)
        float4 av2, bv2;
        if (c + 1 < NCHUNK) {
            const int k0 = (c + 1) * 8;
            av2 = *(const float4*)(aptr + k0);
            bv2 = *(const float4*)(bptr + (size_t)k0 * G4);
        }
        __syncthreads();

        #pragma unroll
        for (int k = 0; k < 8; k++) {
            float4 a0 = *(const float4*)&As[buf][k][tm * 8];
            float4 a1 = *(const float4*)&As[buf][k][tm * 8 + 4];
            ulonglong2 b0 = *(const ulonglong2*)&Bs[buf][k][tn * 8];
            ulonglong2 b1 = *(const ulonglong2*)&Bs[buf][k][tn * 8 + 4];
            u64 bp0 = b0.x, bp1 = b0.y, bp2 = b1.x, bp3 = b1.y;
            float ra[8] = {a0.x, a0.y, a0.z, a0.w, a1.x, a1.y, a1.z, a1.w};
            #pragma unroll
            for (int i = 0; i < 8; i++) {
                u64 ad = pack2_(ra[i]);
                acc2[i][0] = fma2_(ad, bp0, acc2[i][0]);
                acc2[i][1] = fma2_(ad, bp1, acc2[i][1]);
                acc2[i][2] = fma2_(ad, bp2, acc2[i][2]);
                acc2[i][3] = fma2_(ad, bp3, acc2[i][3]);
            }
        }
        av = av2;
        bv = bv2;
    }

    union { float4 f; ulonglong2 u; } bv0, bv1;
    bv0.f = *(const float4*)&bias[n0 + tn * 8];
    bv1.f = *(const float4*)&bias[n0 + tn * 8 + 4];
    u64 bias2[4] = {bv0.u.x, bv0.u.y, bv1.u.x, bv1.u.y};

    #pragma unroll
    for (int i = 0; i < 8; i++) {
        const int row = m0 + tm * 8 + i;
        float* dst = &g_xz[dir][row][n0 + tn * 8];
        double2 o0, o1;
        o0.x = ull_as_d(add2_(acc2[i][0], bias2[0]));
        o0.y = ull_as_d(add2_(acc2[i][1], bias2[1]));
        o1.x = ull_as_d(add2_(acc2[i][2], bias2[2]));
        o1.y = ull_as_d(add2_(acc2[i][3], bias2[3]));
        __stcs((double2*)&dst[0], o0);
        __stcs((double2*)&dst[4], o1);
    }
}

// ---------------------------------------------------------------------------
// Persistent BiLSTM recurrence: ONE kernel runs all 256 steps.
// grid = 128 blocks (co-resident), 256 threads.
// R9 latency cuts:
//  - next-chunk global loads issued BEFORE each __syncthreads
//  - U chunk-0 regs loaded ONCE (step-invariant) -> off the post-barrier path
//  - next step's xz prefetched inside the grid-barrier window
// ---------------------------------------------------------------------------
__device__ __forceinline__ float sigmoidf_(float v) {
    return 1.0f / (1.0f + __expf(-v));
}

#define HSPAD 68   // row pad (words); multiple of 4 keeps 16B alignment

__global__ __launch_bounds__(256, 1)
void persistent_lstm_kernel(const float* __restrict__ Uf,
                            const float* __restrict__ Ub,
                            float* __restrict__ out)
{
    const int bx  = blockIdx.x;
    const int dir = bx >> 6;
    const int j0  = (bx & 63) * 16;
    const float* __restrict__ U = dir ? Ub : Uf;

    __shared__ float Hs[2][16][HSPAD];   // [buf][k][b]
    __shared__ float Us[2][16][HSPAD];   // [buf][k][jj*4 + gate]

    const int tid = threadIdx.x;
    const int tm = tid >> 4;       // 0..15 -> rows (b) tm*4..+3
    const int tn = tid & 15;       // j lane (jj)
    const int j  = j0 + tn;

    const int hb  = tid >> 2;          // 0..63
    const int hk4 = (tid & 3) * 4;     // 0,4,8,12
    const int ukk = tid >> 4;          // 0..15
    const int ulane = tid & 15;

    const float* __restrict__ ubase = U + (size_t)ukk * G4 + j0 + ulane;
    const float* __restrict__ hsrc0 = &g_h[0][dir][hb][hk4];
    const float* __restrict__ hsrc1 = &g_h[1][dir][hb][hk4];

    // ---- step-invariant: U chunk-0 register copy (reused every step)
    const float4 ru0 = make_float4(ubase[0], ubase[HH], ubase[2 * HH], ubase[3 * HH]);

    // ---- phase 0: zero the s=0 read buffer for this block's slice; c -> regs
    #pragma unroll
    for (int r = 0; r < 4; r++)
        __stcg(&g_h[0][dir][tm * 4 + r][j], 0.0f);
    float c_reg[4] = {0.0f, 0.0f, 0.0f, 0.0f};

    // prefetch xz for step 0 while waiting on the barrier
    float xzv[4][4];
    {
        const int t0 = dir ? (TT - 1) : 0;
        #pragma unroll
        for (int r = 0; r < 4; r++) {
            const int b = tm * 4 + r;
            const float* xz = &g_xz[dir][(size_t)b * TT + t0][j];
            xzv[r][0] = __ldcs(xz);
            xzv[r][1] = __ldcs(xz + HH);
            xzv[r][2] = __ldcs(xz + 2 * HH);
            xzv[r][3] = __ldcs(xz + 3 * HH);
        }
    }

    // initial grid barrier
    __syncthreads();
    if (tid == 0) {
        unsigned* p = &g_bar;
        asm volatile("red.release.gpu.global.add.u32 [%0], 1;" :: "l"(p) : "memory");
        unsigned v;
        for (;;) {
            asm volatile("ld.acquire.gpu.global.u32 %0, [%1];" : "=r"(v) : "l"(p) : "memory");
            if (v >= NBLK) break;
            __nanosleep(32);
        }
    }
    __syncthreads();

    // ---- 256 timesteps
    for (int s = 0; s < TT; s++) {
        const int t    = dir ? (TT - 1 - s) : s;
        const int rb   = s & 1;
        const int wbuf = rb ^ 1;
        const float* __restrict__ hsrc = rb ? hsrc1 : hsrc0;

        u64 acc2[2][4];   // [row-pair][gate]
        #pragma unroll
        for (int r2 = 0; r2 < 2; r2++)
            #pragma unroll
            for (int q = 0; q < 4; q++) acc2[r2][q] = 0ull;

        // chunk-0: h load is the only post-barrier dependent load (U from regs)
        float4 rh = __ldcg((const float4*)hsrc);
        float4 ru = ru0;

        const int NCHUNK = HH / 16;  // 64
        for (int c = 0; c < NCHUNK; c++) {
            const int buf = c & 1;
            Hs[buf][hk4 + 0][hb] = rh.x;
            Hs[buf][hk4 + 1][hb] = rh.y;
            Hs[buf][hk4 + 2][hb] = rh.z;
            Hs[buf][hk4 + 3][hb] = rh.w;
            *(float4*)&Us[buf][ukk][ulane * 4] = ru;

            // issue next-chunk loads BEFORE the barrier
            float4 rh2, ru2;
            if (c + 1 < NCHUNK) {
                const int k0 = (c + 1) * 16;
                rh2 = __ldcg((const float4*)(hsrc + k0));
                const float* up = ubase + (size_t)k0 * G4;
                ru2 = make_float4(up[0], up[HH], up[2 * HH], up[3 * HH]);
            }
            __syncthreads();

            #pragma unroll
            for (int k = 0; k < 16; k++) {
                ulonglong2 hp = *(const ulonglong2*)&Hs[buf][k][tm * 4];
                float4 u4 = *(const float4*)&Us[buf][k][tn * 4];
                u64 ui = pack2_(u4.x);
                u64 uf = pack2_(u4.y);
                u64 ug = pack2_(u4.z);
                u64 uo = pack2_(u4.w);
                acc2[0][0] = fma2_(hp.x, ui, acc2[0][0]);
                acc2[0][1] = fma2_(hp.x, uf, acc2[0][1]);
                acc2[0][2] = fma2_(hp.x, ug, acc2[0][2]);
                acc2[0][3] = fma2_(hp.x, uo, acc2[0][3]);
                acc2[1][0] = fma2_(hp.y, ui, acc2[1][0]);
                acc2[1][1] = fma2_(hp.y, uf, acc2[1][1]);
                acc2[1][2] = fma2_(hp.y, ug, acc2[1][2]);
                acc2[1][3] = fma2_(hp.y, uo, acc2[1][3]);
            }
            rh = rh2;
            ru = ru2;
        }

        // unpack accumulators
        float accf[4][4];
        #pragma unroll
        for (int r2 = 0; r2 < 2; r2++)
            #pragma unroll
            for (int q = 0; q < 4; q++)
                unpack2_(acc2[r2][q], accf[2 * r2][q], accf[2 * r2 + 1][q]);

        #pragma unroll
        for (int r = 0; r < 4; r++) {
            const int b = tm * 4 + r;
            float zi = accf[r][0] + xzv[r][0];
            float zf = accf[r][1] + xzv[r][1];
            float zg = accf[r][2] + xzv[r][2];
            float zo = accf[r][3] + xzv[r][3];

            float gi = sigmoidf_(zi);
            float gf = sigmoidf_(zf);
            float gg = tanhf(zg);
            float go = sigmoidf_(zo);

            float cc = gf * c_reg[r] + gi * gg;
            c_reg[r] = cc;
            float h = go * tanhf(cc);

            if (s + 1 < TT)  // last step's h has no reader
                __stcg(&g_h[wbuf][dir][b][j], h);
            __stcs(&out[(size_t)b * (TT * 2 * HH) + (size_t)t * (2 * HH) + dir * HH + j], h);
        }

        // grid barrier with xz prefetch for s+1 tucked into the wait window
        __syncthreads();
        if (tid == 0) {
            unsigned* p = &g_bar;
            asm volatile("red.release.gpu.global.add.u32 [%0], 1;" :: "l"(p) : "memory");
        }
        if (s + 1 < TT) {
            const int tn2 = dir ? (TT - 2 - s) : (s + 1);
            #pragma unroll
            for (int r = 0; r < 4; r++) {
                const int b = tm * 4 + r;
                const float* xz = &g_xz[dir][(size_t)b * TT + tn2][j];
                xzv[r][0] = __ldcs(xz);
                xzv[r][1] = __ldcs(xz + HH);
                xzv[r][2] = __ldcs(xz + 2 * HH);
                xzv[r][3] = __ldcs(xz + 3 * HH);
            }
        }
        if (tid == 0) {
            unsigned* p = &g_bar;
            const unsigned target = NBLK * (unsigned)(s + 2);
            unsigned v;
            for (;;) {
                asm volatile("ld.acquire.gpu.global.u32 %0, [%1];" : "=r"(v) : "l"(p) : "memory");
                if (v >= target) break;
                __nanosleep(32);
            }
        }
        __syncthreads();
    }
}

// ---------------------------------------------------------------------------
// Launch: reset barrier -> input GEMM -> ONE persistent recurrence kernel.
// ---------------------------------------------------------------------------
extern "C" void kernel_launch(void* const* d_in, const int* in_sizes, int n_in,
                              void* d_out, int out_size)
{
    const float* x  = (const float*)d_in[0];
    const float* Wf = (const float*)d_in[1];
    const float* Uf = (const float*)d_in[2];
    const float* bf = (const float*)d_in[3];
    const float* Wb = (const float*)d_in[4];
    const float* Ub = (const float*)d_in[5];
    const float* bb = (const float*)d_in[6];
    float* out = (float*)d_out;

    reset_kernel<<<1, 1>>>();

    dim3 ggrid(64, 128);
    input_gemm_kernel<<<ggrid, 256>>>(x, Wf, bf, Wb, bb);

    persistent_lstm_kernel<<<NBLK, 256>>>(Uf, Ub, out);
}